// round 4
// baseline (speedup 1.0000x reference)
#include <cuda_runtime.h>

// ---------------------------------------------------------------------------
// SSIM loss, fully fused:  1 - mean(ssim_map(img1, img2))
// Images: (32, 3, 512, 512) fp32.  11x11 Gaussian (sigma=1.5), SAME zero pad.
// Strategy: separable blur; horizontal pass from a double-buffered smem row,
// vertical pass from a register-resident 11-row ring with statically rotated
// indices (11-phase unroll) so every tap is an FFMA with immediate weight.
// ---------------------------------------------------------------------------

namespace {
constexpr int H_IMG = 512;
constexpr int W_IMG = 512;
constexpr int TW    = 256;   // strip width (columns per block)
constexpr int NT    = 128;   // threads per block (each owns 2 columns)
constexpr int RC    = 128;   // output rows per block
constexpr int SW    = 272;   // smem staging row stride (>= TW+10, float2-friendly)
constexpr int NPOS  = TW + 10;  // 266 staged positions per row
constexpr int NBLOCKS = 2 * 4 * 96;  // 768
constexpr float C1 = 0.01f * 0.01f;
constexpr float C2 = 0.03f * 0.03f;

// Normalized 1D Gaussian, window 11, sigma 1.5 (matches numpy float64 -> f32)
__device__ constexpr float WG[11] = {
    0.00102838f, 0.00759876f, 0.03600078f, 0.10936069f, 0.21300554f,
    0.26601173f,
    0.21300554f, 0.10936069f, 0.03600078f, 0.00759876f, 0.00102838f
};
}  // namespace

__device__ float g_partials[NBLOCKS];

__device__ __forceinline__ void load_pos(const float* __restrict__ p1,
                                         const float* __restrict__ p2,
                                         int r, int c, float& a, float& b) {
    a = 0.f;
    b = 0.f;
    if ((unsigned)r < (unsigned)H_IMG && (unsigned)c < (unsigned)W_IMG) {
        int idx = r * W_IMG + c;
        a = __ldg(p1 + idx);
        b = __ldg(p2 + idx);
    }
}

__global__ void __launch_bounds__(NT)
ssim_main(const float* __restrict__ img1, const float* __restrict__ img2) {
    const int t     = threadIdx.x;
    const int strip = blockIdx.x;   // 0..1
    const int chunk = blockIdx.y;   // 0..3
    const int plane = blockIdx.z;   // 0..95

    const int x0  = strip * TW - 5;   // global col of staging index 0
    const int gy0 = chunk * RC;       // first output row of this block

    const float* p1 = img1 + (size_t)plane * H_IMG * W_IMG;
    const float* p2 = img2 + (size_t)plane * H_IMG * W_IMG;

    // staging: [double-buffer][map: x,y,xx,yy,xy][position]
    __shared__ __align__(16) float sb[2][5][SW];
    __shared__ float warp_sums[NT / 32];

    // register ring: 11 rows of horizontally-blurred values, 5 maps, 2 cols
    float ring[11][5][2];

    float lsum = 0.f;

    // Prefetch staging row for iteration i=0 (image row gy0-5)
    float ax0, ax1, ax2, ay0, ay1, ay2;
    {
        int r = gy0 - 5;
        load_pos(p1, p2, r, x0 + t,        ax0, ay0);
        load_pos(p1, p2, r, x0 + t + 128,  ax1, ay1);
        if (t < NPOS - 256) load_pos(p1, p2, r, x0 + t + 256, ax2, ay2);
        else { ax2 = 0.f; ay2 = 0.f; }
    }

    // 143 = 13 * 11 iterations; output rows produced for i in [10, 138)
    for (int ib = 0; ib < 143; ib += 11) {
#pragma unroll
        for (int jj = 0; jj < 11; ++jj) {
            const int i   = ib + jj;
            const int buf = i & 1;

            // Prefetch next staging row (hides DRAM latency behind compute)
            float bx0, bx1, bx2, by0, by1, by2;
            {
                int r = gy0 - 4 + i;  // (gy0 - 5) + (i + 1)
                load_pos(p1, p2, r, x0 + t,       bx0, by0);
                load_pos(p1, p2, r, x0 + t + 128, bx1, by1);
                if (t < NPOS - 256) load_pos(p1, p2, r, x0 + t + 256, bx2, by2);
                else { bx2 = 0.f; by2 = 0.f; }
            }

            // Stage current row: x, y, xx, yy, xy
            {
                float xv = ax0, yv = ay0;
                sb[buf][0][t] = xv;        sb[buf][1][t] = yv;
                sb[buf][2][t] = xv * xv;   sb[buf][3][t] = yv * yv;
                sb[buf][4][t] = xv * yv;
                xv = ax1; yv = ay1;
                sb[buf][0][t + 128] = xv;      sb[buf][1][t + 128] = yv;
                sb[buf][2][t + 128] = xv * xv; sb[buf][3][t + 128] = yv * yv;
                sb[buf][4][t + 128] = xv * yv;
                if (t < NPOS - 256) {
                    xv = ax2; yv = ay2;
                    sb[buf][0][t + 256] = xv;      sb[buf][1][t + 256] = yv;
                    sb[buf][2][t + 256] = xv * xv; sb[buf][3][t + 256] = yv * yv;
                    sb[buf][4][t + 256] = xv * yv;
                }
            }
            __syncthreads();

            // Horizontal 11-tap blur -> ring slot jj (all weights immediate)
#pragma unroll
            for (int m = 0; m < 5; ++m) {
                const float* rowp = &sb[buf][m][2 * t];
                float v[12];
#pragma unroll
                for (int k = 0; k < 6; ++k) {
                    float2 q = *(const float2*)(rowp + 2 * k);  // 8B aligned
                    v[2 * k]     = q.x;
                    v[2 * k + 1] = q.y;
                }
                float A = 0.f, B = 0.f;
#pragma unroll
                for (int k = 0; k < 11; ++k) {
                    A = fmaf(WG[k], v[k],     A);
                    B = fmaf(WG[k], v[k + 1], B);
                }
                ring[jj][m][0] = A;
                ring[jj][m][1] = B;
            }

            // Vertical blur straight from registers + SSIM + accumulate
            if (i >= 10 && i < 138) {
                float s0[5], s1[5];
#pragma unroll
                for (int q = 0; q < 5; ++q) { s0[q] = 0.f; s1[q] = 0.f; }
#pragma unroll
                for (int m = 0; m < 11; ++m) {
                    const int widx = 10 - ((jj - m + 11) % 11);  // compile-time
                    const float w = WG[widx];
#pragma unroll
                    for (int q = 0; q < 5; ++q) {
                        s0[q] = fmaf(w, ring[m][q][0], s0[q]);
                        s1[q] = fmaf(w, ring[m][q][1], s1[q]);
                    }
                }
                {
                    float mu1 = s0[0], mu2 = s0[1];
                    float m11 = mu1 * mu1, m22 = mu2 * mu2, m12 = mu1 * mu2;
                    float sg1 = s0[2] - m11, sg2 = s0[3] - m22, sg12 = s0[4] - m12;
                    float num = (2.f * m12 + C1) * (2.f * sg12 + C2);
                    float den = (m11 + m22 + C1) * (sg1 + sg2 + C2);
                    lsum += __fdividef(num, den);
                }
                {
                    float mu1 = s1[0], mu2 = s1[1];
                    float m11 = mu1 * mu1, m22 = mu2 * mu2, m12 = mu1 * mu2;
                    float sg1 = s1[2] - m11, sg2 = s1[3] - m22, sg12 = s1[4] - m12;
                    float num = (2.f * m12 + C1) * (2.f * sg12 + C2);
                    float den = (m11 + m22 + C1) * (sg1 + sg2 + C2);
                    lsum += __fdividef(num, den);
                }
            }

            // rotate prefetch registers
            ax0 = bx0; ax1 = bx1; ax2 = bx2;
            ay0 = by0; ay1 = by1; ay2 = by2;
        }
    }

    // Deterministic block reduction: warp shuffle tree + smem
#pragma unroll
    for (int off = 16; off > 0; off >>= 1)
        lsum += __shfl_down_sync(0xffffffffu, lsum, off);
    if ((t & 31) == 0) warp_sums[t >> 5] = lsum;
    __syncthreads();
    if (t == 0) {
        float s = warp_sums[0] + warp_sums[1] + warp_sums[2] + warp_sums[3];
        g_partials[(plane * 4 + chunk) * 2 + strip] = s;
    }
}

__global__ void ssim_finalize(float* __restrict__ out) {
    __shared__ double sd[256];
    int t = threadIdx.x;
    double v = 0.0;
    for (int i = t; i < NBLOCKS; i += 256) v += (double)g_partials[i];
    sd[t] = v;
    __syncthreads();
    for (int off = 128; off > 0; off >>= 1) {
        if (t < off) sd[t] += sd[t + off];
        __syncthreads();
    }
    if (t == 0) {
        const double n = 32.0 * 3.0 * 512.0 * 512.0;  // 25165824
        out[0] = (float)(1.0 - sd[0] / n);
    }
}

extern "C" void kernel_launch(void* const* d_in, const int* in_sizes, int n_in,
                              void* d_out, int out_size) {
    (void)in_sizes; (void)n_in; (void)out_size;
    const float* img1 = (const float*)d_in[0];
    const float* img2 = (const float*)d_in[1];
    dim3 grid(2, 4, 96);  // strips x row-chunks x (N*C) planes
    ssim_main<<<grid, NT>>>(img1, img2);
    ssim_finalize<<<1, 256>>>((float*)d_out);
}

// round 5
// speedup vs baseline: 1.0643x; 1.0643x over previous
#include <cuda_runtime.h>

// ---------------------------------------------------------------------------
// SSIM loss, fully fused:  out = 1 - mean(ssim_map(img1, img2))
// (32,3,512,512) fp32, 11x11 Gaussian sigma=1.5, SAME zero padding.
//
// Design: warp-autonomous 64-column strips. Per row: stage {x,y,xx,yy,xy}
// into a warp-private double-buffered smem row (1 __syncwarp/row), 11-tap
// horizontal blur (all FFMA-imm), push into a register-resident 11-row ring,
// 11-tap vertical blur from registers with statically rotated indices
// (row_step<JJ> template, 11-phase), SSIM epilogue, accumulate.
// Boundary handling is branch-free: clamped addresses + {0,1} masks folded
// into the staging multiplies. Final scalar reduction fused via last-block
// atomic counter (deterministic fixed-order double sum, self-resetting).
// ---------------------------------------------------------------------------

namespace {
constexpr int HW      = 512;
constexpr int NT      = 128;                 // 4 warps per CTA
constexpr int RC      = 256;                 // output rows per CTA
constexpr int WSTRIDE = 80;                  // smem floats per map row (>=74)
constexpr int NCTAS   = 2 * 2 * 96;          // strips x chunks x planes = 384
constexpr int NPART   = NCTAS * 4;           // one partial per warp = 1536
constexpr float C1    = 0.01f * 0.01f;
constexpr float C2    = 0.03f * 0.03f;

// Normalized 1D Gaussian, window 11, sigma 1.5
__device__ constexpr float WG[11] = {
    0.00102838f, 0.00759876f, 0.03600078f, 0.10936069f, 0.21300554f,
    0.26601173f,
    0.21300554f, 0.10936069f, 0.03600078f, 0.00759876f, 0.00102838f
};
}  // namespace

__device__ float g_partials[NPART];
__device__ int   g_count = 0;

// One row of the pipeline. JJ = i mod 11 (compile-time ring phase).
template <int JJ>
__device__ __forceinline__ void row_step(
    int i, int gy0, int lane,
    const char* __restrict__ pc1, const char* __restrict__ pc2,
    int off0, int off1, int off2,
    float cm0, float cm1, float cm2,
    float* __restrict__ sw,
    float (&ring)[11][5][2],
    float (&pa)[6], float& arm,
    float& lsum)
{
    // ---- prefetch raw row (gy0-4+i) into pb (hides DRAM latency) ----
    float pb[6];
    float brm;
    {
        int rr = gy0 - 4 + i;
        int rc = rr < 0 ? 0 : (rr > 511 ? 511 : rr);
        brm = (rr == rc) ? 1.f : 0.f;
        const char* r1 = pc1 + rc * 2048;
        const char* r2 = pc2 + rc * 2048;
        pb[0] = *(const float*)(r1 + off0);
        pb[1] = *(const float*)(r2 + off0);
        pb[2] = *(const float*)(r1 + off1);
        pb[3] = *(const float*)(r2 + off1);
        if (lane < 10) {
            pb[4] = *(const float*)(r1 + off2);
            pb[5] = *(const float*)(r2 + off2);
        } else {
            pb[4] = 0.f; pb[5] = 0.f;
        }
    }

    // ---- stage row i (in pa) into warp-private smem buffer ----
    float* sbuf = sw + (i & 1) * (5 * WSTRIDE);
    {
        float m0 = cm0 * arm, m1 = cm1 * arm, m2 = cm2 * arm;
        float xm = pa[0] * m0, ym = pa[1] * m0;
        int p = lane;
        sbuf[0 * WSTRIDE + p] = xm;      sbuf[1 * WSTRIDE + p] = ym;
        sbuf[2 * WSTRIDE + p] = xm * xm; sbuf[3 * WSTRIDE + p] = ym * ym;
        sbuf[4 * WSTRIDE + p] = xm * ym;
        xm = pa[2] * m1; ym = pa[3] * m1; p = lane + 32;
        sbuf[0 * WSTRIDE + p] = xm;      sbuf[1 * WSTRIDE + p] = ym;
        sbuf[2 * WSTRIDE + p] = xm * xm; sbuf[3 * WSTRIDE + p] = ym * ym;
        sbuf[4 * WSTRIDE + p] = xm * ym;
        if (lane < 10) {
            xm = pa[4] * m2; ym = pa[5] * m2; p = lane + 64;
            sbuf[0 * WSTRIDE + p] = xm;      sbuf[1 * WSTRIDE + p] = ym;
            sbuf[2 * WSTRIDE + p] = xm * xm; sbuf[3 * WSTRIDE + p] = ym * ym;
            sbuf[4 * WSTRIDE + p] = xm * ym;
        }
    }
    __syncwarp();

    // ---- horizontal 11-tap blur (FFMA-imm) -> ring slot JJ ----
#pragma unroll
    for (int m = 0; m < 5; ++m) {
        const float* rp = sbuf + m * WSTRIDE + 2 * lane;
        float v[12];
#pragma unroll
        for (int k = 0; k < 6; ++k) {
            float2 q = *(const float2*)(rp + 2 * k);  // 8B aligned
            v[2 * k]     = q.x;
            v[2 * k + 1] = q.y;
        }
        float A = 0.f, B = 0.f;
#pragma unroll
        for (int k = 0; k < 11; ++k) {
            A = fmaf(WG[k], v[k],     A);
            B = fmaf(WG[k], v[k + 1], B);
        }
        ring[JJ][m][0] = A;
        ring[JJ][m][1] = B;
    }

    // ---- vertical 11-tap blur from registers + SSIM + accumulate ----
    if (i >= 10) {
        float s0[5] = {0.f, 0.f, 0.f, 0.f, 0.f};
        float s1[5] = {0.f, 0.f, 0.f, 0.f, 0.f};
#pragma unroll
        for (int m = 0; m < 11; ++m) {
            const float w = WG[10 - ((JJ - m + 11) % 11)];  // compile-time
#pragma unroll
            for (int q = 0; q < 5; ++q) {
                s0[q] = fmaf(w, ring[m][q][0], s0[q]);
                s1[q] = fmaf(w, ring[m][q][1], s1[q]);
            }
        }
        {
            float mu1 = s0[0], mu2 = s0[1];
            float m11 = mu1 * mu1, m22 = mu2 * mu2, m12 = mu1 * mu2;
            float sg1 = s0[2] - m11, sg2 = s0[3] - m22, sg12 = s0[4] - m12;
            float num = (2.f * m12 + C1) * (2.f * sg12 + C2);
            float den = (m11 + m22 + C1) * (sg1 + sg2 + C2);
            lsum += __fdividef(num, den);
        }
        {
            float mu1 = s1[0], mu2 = s1[1];
            float m11 = mu1 * mu1, m22 = mu2 * mu2, m12 = mu1 * mu2;
            float sg1 = s1[2] - m11, sg2 = s1[3] - m22, sg12 = s1[4] - m12;
            float num = (2.f * m12 + C1) * (2.f * sg12 + C2);
            float den = (m11 + m22 + C1) * (sg1 + sg2 + C2);
            lsum += __fdividef(num, den);
        }
    }

    // ---- rotate prefetch ----
#pragma unroll
    for (int k = 0; k < 6; ++k) pa[k] = pb[k];
    arm = brm;
}

__global__ void __launch_bounds__(NT, 3)
ssim_kernel(const float* __restrict__ img1, const float* __restrict__ img2,
            float* __restrict__ out)
{
    __shared__ __align__(16) float sb[4][2 * 5 * WSTRIDE];  // per-warp staging
    __shared__ double sdbl[NT];
    __shared__ int    s_last;

    const int t     = threadIdx.x;
    const int w     = t >> 5;
    const int lane  = t & 31;
    const int strip = blockIdx.x;   // 0..1
    const int chunk = blockIdx.y;   // 0..1
    const int plane = blockIdx.z;   // 0..95

    const int gy0  = chunk * RC;
    const int col0 = strip * 256 + w * 64 - 5;  // global col of staging pos 0

    const char* pc1 = (const char*)(img1 + (size_t)plane * HW * HW);
    const char* pc2 = (const char*)(img2 + (size_t)plane * HW * HW);

    // Per-slot clamped byte offsets + validity masks (computed once)
    int   off0, off1, off2;
    float cm0, cm1, cm2;
    {
        int c;
        c = col0 + lane;
        cm0  = (c >= 0 && c < 512) ? 1.f : 0.f;
        off0 = (c < 0 ? 0 : (c > 511 ? 511 : c)) * 4;
        c = col0 + lane + 32;
        cm1  = (c >= 0 && c < 512) ? 1.f : 0.f;
        off1 = (c < 0 ? 0 : (c > 511 ? 511 : c)) * 4;
        c = col0 + lane + 64;
        cm2  = (c >= 0 && c < 512) ? 1.f : 0.f;
        off2 = (c < 0 ? 0 : (c > 511 ? 511 : c)) * 4;
    }

    float* sw_ = &sb[w][0];
    float ring[11][5][2];
    float pa[6];
    float arm;
    float lsum = 0.f;

    // Initial prefetch: raw row gy0-5 (i = 0)
    {
        int rr = gy0 - 5;
        int rc = rr < 0 ? 0 : rr;  // never > 511 here
        arm = (rr == rc) ? 1.f : 0.f;
        const char* r1 = pc1 + rc * 2048;
        const char* r2 = pc2 + rc * 2048;
        pa[0] = *(const float*)(r1 + off0);
        pa[1] = *(const float*)(r2 + off0);
        pa[2] = *(const float*)(r1 + off1);
        pa[3] = *(const float*)(r2 + off1);
        if (lane < 10) {
            pa[4] = *(const float*)(r1 + off2);
            pa[5] = *(const float*)(r2 + off2);
        } else {
            pa[4] = 0.f; pa[5] = 0.f;
        }
    }

#define RS(I, J) row_step<J>((I), gy0, lane, pc1, pc2, off0, off1, off2, \
                             cm0, cm1, cm2, sw_, ring, pa, arm, lsum)

    // 266 iterations total = 24*11 + 2; outputs produced for i in [10, 266)
    for (int ib = 0; ib < 264; ib += 11) {
        RS(ib + 0, 0);  RS(ib + 1, 1);  RS(ib + 2, 2);  RS(ib + 3, 3);
        RS(ib + 4, 4);  RS(ib + 5, 5);  RS(ib + 6, 6);  RS(ib + 7, 7);
        RS(ib + 8, 8);  RS(ib + 9, 9);  RS(ib + 10, 10);
    }
    RS(264, 0);
    RS(265, 1);
#undef RS

    // ---- deterministic warp reduction -> per-warp global partial ----
#pragma unroll
    for (int o = 16; o > 0; o >>= 1)
        lsum += __shfl_down_sync(0xffffffffu, lsum, o);
    if (lane == 0)
        g_partials[(((plane * 2) + chunk) * 2 + strip) * 4 + w] = lsum;
    __syncthreads();

    // ---- last-block finalize (fused; deterministic; self-resetting) ----
    if (t == 0) {
        __threadfence();
        s_last = (atomicAdd(&g_count, 1) == NCTAS - 1) ? 1 : 0;
    }
    __syncthreads();
    if (s_last) {
        __threadfence();
        double acc = 0.0;
#pragma unroll
        for (int k = 0; k < NPART / NT; ++k)
            acc += (double)g_partials[t * (NPART / NT) + k];
        sdbl[t] = acc;
        __syncthreads();
        for (int o = 64; o > 0; o >>= 1) {
            if (t < o) sdbl[t] += sdbl[t + o];
            __syncthreads();
        }
        if (t == 0) {
            out[0] = (float)(1.0 - sdbl[0] / 25165824.0);  // 32*3*512*512
            g_count = 0;  // reset for next graph replay
        }
    }
}

extern "C" void kernel_launch(void* const* d_in, const int* in_sizes, int n_in,
                              void* d_out, int out_size) {
    (void)in_sizes; (void)n_in; (void)out_size;
    const float* img1 = (const float*)d_in[0];
    const float* img2 = (const float*)d_in[1];
    dim3 grid(2, 2, 96);  // strips x row-chunks x (N*C) planes
    ssim_kernel<<<grid, NT>>>(img1, img2, (float*)d_out);
}

// round 6
// speedup vs baseline: 1.3072x; 1.2282x over previous
#include <cuda_runtime.h>

// ---------------------------------------------------------------------------
// SSIM loss, fully fused:  out = 1 - mean(ssim_map(img1, img2))
// (32,3,512,512) fp32, 11x11 Gaussian sigma=1.5, SAME zero padding.
//
// Key algebraic reduction: SSIM only needs sigma1_sq + sigma2_sq, so we blur
// FOUR maps {x, y, x*x + y*y, x*y} instead of five (-20% FFMA / regs / smem).
//
// Warp-autonomous 64-col strips; per row: stage maps into warp-private
// double-buffered smem (1 __syncwarp/row), 11-tap horizontal blur (FFMA-imm),
// register ring of 11 h-blurred rows, 11-tap vertical blur with statically
// rotated ring indices (row_step<JJ>), SSIM epilogue, accumulate.
// Branch-free borders: clamped addresses + {0,1} masks folded into staging.
// Final reduction fused via last-block atomic counter (deterministic,
// fixed-order double sum, self-resetting for graph replay).
// ---------------------------------------------------------------------------

namespace {
constexpr int HW      = 512;
constexpr int NT      = 128;                 // 4 warps per CTA
constexpr int RC      = 256;                 // output rows per CTA
constexpr int WSTRIDE = 80;                  // smem floats per map row (>=74)
constexpr int NCTAS   = 2 * 2 * 96;          // strips x chunks x planes = 384
constexpr int NPART   = NCTAS * 4;           // one partial per warp = 1536
constexpr float C1    = 0.01f * 0.01f;
constexpr float C2    = 0.03f * 0.03f;

// Normalized 1D Gaussian, window 11, sigma 1.5
__device__ constexpr float WG[11] = {
    0.00102838f, 0.00759876f, 0.03600078f, 0.10936069f, 0.21300554f,
    0.26601173f,
    0.21300554f, 0.10936069f, 0.03600078f, 0.00759876f, 0.00102838f
};
}  // namespace

__device__ float g_partials[NPART];
__device__ int   g_count = 0;

// One row of the pipeline. JJ = i mod 11 (compile-time ring phase).
template <int JJ>
__device__ __forceinline__ void row_step(
    int i, int gy0, int lane,
    const char* __restrict__ pc1, const char* __restrict__ pc2,
    int off0, int off1, int off2,
    float cm0, float cm1, float cm2,
    float* __restrict__ sw,
    float (&ring)[11][4][2],
    float (&pa)[6], float& arm,
    float& lsum)
{
    // ---- prefetch raw row (gy0-4+i) into pb (hides DRAM latency) ----
    float pb[6];
    float brm;
    {
        int rr = gy0 - 4 + i;
        int rc = rr < 0 ? 0 : (rr > 511 ? 511 : rr);
        brm = (rr == rc) ? 1.f : 0.f;
        const char* r1 = pc1 + rc * 2048;
        const char* r2 = pc2 + rc * 2048;
        pb[0] = *(const float*)(r1 + off0);
        pb[1] = *(const float*)(r2 + off0);
        pb[2] = *(const float*)(r1 + off1);
        pb[3] = *(const float*)(r2 + off1);
        if (lane < 10) {
            pb[4] = *(const float*)(r1 + off2);
            pb[5] = *(const float*)(r2 + off2);
        } else {
            pb[4] = 0.f; pb[5] = 0.f;
        }
    }

    // ---- stage row i (in pa): maps {x, y, x*x+y*y, x*y} ----
    float* sbuf = sw + (i & 1) * (4 * WSTRIDE);
    {
        float m0 = cm0 * arm, m1 = cm1 * arm, m2 = cm2 * arm;
        float xm = pa[0] * m0, ym = pa[1] * m0;
        int p = lane;
        sbuf[0 * WSTRIDE + p] = xm;
        sbuf[1 * WSTRIDE + p] = ym;
        sbuf[2 * WSTRIDE + p] = fmaf(xm, xm, ym * ym);
        sbuf[3 * WSTRIDE + p] = xm * ym;
        xm = pa[2] * m1; ym = pa[3] * m1; p = lane + 32;
        sbuf[0 * WSTRIDE + p] = xm;
        sbuf[1 * WSTRIDE + p] = ym;
        sbuf[2 * WSTRIDE + p] = fmaf(xm, xm, ym * ym);
        sbuf[3 * WSTRIDE + p] = xm * ym;
        if (lane < 10) {
            xm = pa[4] * m2; ym = pa[5] * m2; p = lane + 64;
            sbuf[0 * WSTRIDE + p] = xm;
            sbuf[1 * WSTRIDE + p] = ym;
            sbuf[2 * WSTRIDE + p] = fmaf(xm, xm, ym * ym);
            sbuf[3 * WSTRIDE + p] = xm * ym;
        }
    }
    __syncwarp();

    // ---- horizontal 11-tap blur (FFMA-imm) -> ring slot JJ ----
#pragma unroll
    for (int m = 0; m < 4; ++m) {
        const float* rp = sbuf + m * WSTRIDE + 2 * lane;
        float v[12];
#pragma unroll
        for (int k = 0; k < 6; ++k) {
            float2 q = *(const float2*)(rp + 2 * k);  // 8B aligned
            v[2 * k]     = q.x;
            v[2 * k + 1] = q.y;
        }
        float A = 0.f, B = 0.f;
#pragma unroll
        for (int k = 0; k < 11; ++k) {
            A = fmaf(WG[k], v[k],     A);
            B = fmaf(WG[k], v[k + 1], B);
        }
        ring[JJ][m][0] = A;
        ring[JJ][m][1] = B;
    }

    // ---- vertical 11-tap blur from registers + SSIM + accumulate ----
    if (i >= 10) {
        float s0[4] = {0.f, 0.f, 0.f, 0.f};
        float s1[4] = {0.f, 0.f, 0.f, 0.f};
#pragma unroll
        for (int m = 0; m < 11; ++m) {
            const float w = WG[10 - ((JJ - m + 11) % 11)];  // compile-time
#pragma unroll
            for (int q = 0; q < 4; ++q) {
                s0[q] = fmaf(w, ring[m][q][0], s0[q]);
                s1[q] = fmaf(w, ring[m][q][1], s1[q]);
            }
        }
        {
            float mu1 = s0[0], mu2 = s0[1], bss = s0[2], bxy = s0[3];
            float m12 = mu1 * mu2;
            float msq = fmaf(mu1, mu1, mu2 * mu2);
            float num = fmaf(2.f, m12, C1) * fmaf(2.f, bxy - m12, C2);
            float den = (msq + C1) * (bss - msq + C2);
            lsum += __fdividef(num, den);
        }
        {
            float mu1 = s1[0], mu2 = s1[1], bss = s1[2], bxy = s1[3];
            float m12 = mu1 * mu2;
            float msq = fmaf(mu1, mu1, mu2 * mu2);
            float num = fmaf(2.f, m12, C1) * fmaf(2.f, bxy - m12, C2);
            float den = (msq + C1) * (bss - msq + C2);
            lsum += __fdividef(num, den);
        }
    }

    // ---- rotate prefetch ----
#pragma unroll
    for (int k = 0; k < 6; ++k) pa[k] = pb[k];
    arm = brm;
}

__global__ void __launch_bounds__(NT, 3)
ssim_kernel(const float* __restrict__ img1, const float* __restrict__ img2,
            float* __restrict__ out)
{
    __shared__ __align__(16) float sb[4][2 * 4 * WSTRIDE];  // per-warp staging
    __shared__ double sdbl[NT];
    __shared__ int    s_last;

    const int t     = threadIdx.x;
    const int w     = t >> 5;
    const int lane  = t & 31;
    const int strip = blockIdx.x;   // 0..1
    const int chunk = blockIdx.y;   // 0..1
    const int plane = blockIdx.z;   // 0..95

    const int gy0  = chunk * RC;
    const int col0 = strip * 256 + w * 64 - 5;  // global col of staging pos 0

    const char* pc1 = (const char*)(img1 + (size_t)plane * HW * HW);
    const char* pc2 = (const char*)(img2 + (size_t)plane * HW * HW);

    // Per-slot clamped byte offsets + validity masks (computed once)
    int   off0, off1, off2;
    float cm0, cm1, cm2;
    {
        int c;
        c = col0 + lane;
        cm0  = (c >= 0 && c < 512) ? 1.f : 0.f;
        off0 = (c < 0 ? 0 : (c > 511 ? 511 : c)) * 4;
        c = col0 + lane + 32;
        cm1  = (c >= 0 && c < 512) ? 1.f : 0.f;
        off1 = (c < 0 ? 0 : (c > 511 ? 511 : c)) * 4;
        c = col0 + lane + 64;
        cm2  = (c >= 0 && c < 512) ? 1.f : 0.f;
        off2 = (c < 0 ? 0 : (c > 511 ? 511 : c)) * 4;
    }

    float* sw_ = &sb[w][0];
    float ring[11][4][2];
    float pa[6];
    float arm;
    float lsum = 0.f;

    // Initial prefetch: raw row gy0-5 (i = 0)
    {
        int rr = gy0 - 5;
        int rc = rr < 0 ? 0 : rr;  // never > 511 here
        arm = (rr == rc) ? 1.f : 0.f;
        const char* r1 = pc1 + rc * 2048;
        const char* r2 = pc2 + rc * 2048;
        pa[0] = *(const float*)(r1 + off0);
        pa[1] = *(const float*)(r2 + off0);
        pa[2] = *(const float*)(r1 + off1);
        pa[3] = *(const float*)(r2 + off1);
        if (lane < 10) {
            pa[4] = *(const float*)(r1 + off2);
            pa[5] = *(const float*)(r2 + off2);
        } else {
            pa[4] = 0.f; pa[5] = 0.f;
        }
    }

#define RS(I, J) row_step<J>((I), gy0, lane, pc1, pc2, off0, off1, off2, \
                             cm0, cm1, cm2, sw_, ring, pa, arm, lsum)

    // 266 iterations total = 24*11 + 2; outputs produced for i in [10, 266)
    for (int ib = 0; ib < 264; ib += 11) {
        RS(ib + 0, 0);  RS(ib + 1, 1);  RS(ib + 2, 2);  RS(ib + 3, 3);
        RS(ib + 4, 4);  RS(ib + 5, 5);  RS(ib + 6, 6);  RS(ib + 7, 7);
        RS(ib + 8, 8);  RS(ib + 9, 9);  RS(ib + 10, 10);
    }
    RS(264, 0);
    RS(265, 1);
#undef RS

    // ---- deterministic warp reduction -> per-warp global partial ----
#pragma unroll
    for (int o = 16; o > 0; o >>= 1)
        lsum += __shfl_down_sync(0xffffffffu, lsum, o);
    if (lane == 0)
        g_partials[(((plane * 2) + chunk) * 2 + strip) * 4 + w] = lsum;
    __syncthreads();

    // ---- last-block finalize (fused; deterministic; self-resetting) ----
    if (t == 0) {
        __threadfence();
        s_last = (atomicAdd(&g_count, 1) == NCTAS - 1) ? 1 : 0;
    }
    __syncthreads();
    if (s_last) {
        __threadfence();
        double acc = 0.0;
#pragma unroll
        for (int k = 0; k < NPART / NT; ++k)
            acc += (double)g_partials[t * (NPART / NT) + k];
        sdbl[t] = acc;
        __syncthreads();
        for (int o = 64; o > 0; o >>= 1) {
            if (t < o) sdbl[t] += sdbl[t + o];
            __syncthreads();
        }
        if (t == 0) {
            out[0] = (float)(1.0 - sdbl[0] / 25165824.0);  // 32*3*512*512
            g_count = 0;  // reset for next graph replay
        }
    }
}

extern "C" void kernel_launch(void* const* d_in, const int* in_sizes, int n_in,
                              void* d_out, int out_size) {
    (void)in_sizes; (void)n_in; (void)out_size;
    const float* img1 = (const float*)d_in[0];
    const float* img2 = (const float*)d_in[1];
    dim3 grid(2, 2, 96);  // strips x row-chunks x (N*C) planes
    ssim_kernel<<<grid, NT>>>(img1, img2, (float*)d_out);
}